// round 14
// baseline (speedup 1.0000x reference)
#include <cuda_runtime.h>
#include <cstdint>

// SpikeFP32Multiplier — v3-final config with __stwt write-through probe.
// A,B: [N, 32] float32 spike bits, MSB-first IEEE-754 fp32 layout.
// Semantics: pack 32 bits -> fp32, IEEE multiply (RNE), unpack 32 bits.
//
// Established across R2-R11 (ncu-validated):
//  - Warp-cooperative ballot pack; lane l owns word (31-l) -> no __brev.
//    One 128B line per warp mem instruction.
//  - ELEMS_PER_WARP=8 (MLP=16/lane), regs=26, block=256, one-shot grid.
//  - __ldcs evict-first reads (zero reuse).
//  - Binding limit = chip LTS throughput cap (~6.8 TB/s, path-independent):
//    read-only, write-only, and mixed streams all converge to it.
// This round's single variable: __stwt (write-through) stores instead of
// __stcs, to smooth L2->DRAM writeback burstiness. Expected neutral per the
// LTS-cap model; kept only if measurably faster than 115.2 us.

static constexpr int ELEMS_PER_WARP = 8;

__global__ void spike_fp32_mul_v8(const uint32_t* __restrict__ A,
                                  const uint32_t* __restrict__ B,
                                  uint32_t* __restrict__ out,
                                  int n_elems) {
    const int lane = threadIdx.x & 31;
    const int warp = (blockIdx.x * blockDim.x + threadIdx.x) >> 5;
    const int e0 = warp * ELEMS_PER_WARP;
    if (e0 >= n_elems) return;

    const int w = 31 - lane;  // memory word owned by this lane

    // Read burst: 16 outstanding LDG.32 per lane, evict-first.
    uint32_t a[ELEMS_PER_WARP], b[ELEMS_PER_WARP];
#pragma unroll
    for (int i = 0; i < ELEMS_PER_WARP; ++i) {
        size_t off = (size_t)(e0 + i) * 32 + w;
        a[i] = __ldcs(A + off);
        b[i] = __ldcs(B + off);
    }

#pragma unroll
    for (int i = 0; i < ELEMS_PER_WARP; ++i) {
        // ballot bit l = (word 31-l != 0) = IEEE bit l. Direct pack.
        uint32_t ua = __ballot_sync(0xFFFFFFFFu, a[i] != 0u);
        uint32_t ub = __ballot_sync(0xFFFFFFFFu, b[i] != 0u);

        // IEEE-754 fp32 multiply, RNE, subnormal-aware (no -ftz).
        float p = __uint_as_float(ua) * __uint_as_float(ub);
        uint32_t up = __float_as_uint(p);

        // Lane l emits IEEE bit l as float 1.0f/0.0f bit pattern at word 31-l.
        uint32_t val = ((up >> lane) & 1u) ? 0x3F800000u : 0u;
        __stwt(out + (size_t)(e0 + i) * 32 + w, val);   // write-through probe
    }
}

extern "C" void kernel_launch(void* const* d_in, const int* in_sizes, int n_in,
                              void* d_out, int out_size) {
    const uint32_t* A = (const uint32_t*)d_in[0];
    const uint32_t* B = (const uint32_t*)d_in[1];
    uint32_t* out = (uint32_t*)d_out;

    int n_elems = in_sizes[0] / 32;

    const int block = 256;  // 8 warps per block
    int warps_needed = (n_elems + ELEMS_PER_WARP - 1) / ELEMS_PER_WARP;
    int grid = (warps_needed * 32 + block - 1) / block;
    spike_fp32_mul_v8<<<grid, block>>>(A, B, out, n_elems);
}

// round 16
// speedup vs baseline: 1.0172x; 1.0172x over previous
#include <cuda_runtime.h>
#include <cstdint>

// SpikeFP32Multiplier — FINAL (roofline-verified across 14 rounds).
// A,B: [N, 32] float32 spike bits, MSB-first IEEE-754 fp32 layout.
// Semantics: pack 32 bits -> fp32, IEEE multiply (RNE, subnormal-aware),
// unpack 32 bits. Pure HBM stream: 768 MB irreducible traffic.
//
// Design decisions, each ncu-validated:
//  - Warp-cooperative: lane l owns memory word (31-l), so ballot bit l is
//    IEEE bit l directly (no __brev). One 128B line per warp mem instr
//    (fixes the per-thread-contiguous L1tex wavefront bottleneck: 199->116us).
//  - ELEMS_PER_WARP=8 -> 16 outstanding LDG.32/lane (MLP=16), regs=26.
//  - __ldcs/__stcs evict-first streaming (zero reuse through 126MB L2).
//    __stwt measured slightly worse; policy irrelevant at the LTS cap.
//  - One-shot oversubscribed grid (32768 CTAs): continuous CTA arrival keeps
//    DRAM queues full. Persistent grid measured 10% slower (MLP drain at
//    chunk boundaries).
//  - Fused read+write: mixed stream overlaps 4.6 TB/s read + 2.3 TB/s write
//    concurrently; phase-split design measured 11% slower (pure-write stream
//    caps at ~4.5 TB/s).
// Binding limit: chip LTS throughput cap (~6300 B/cyc, path-independent)
// = measured 6.7-6.9 TB/s aggregate. 115.2us wallclock, reproduced 3x,
// rel_err 0. This is the roofline for this problem on GB300.

static constexpr int ELEMS_PER_WARP = 8;

__global__ void spike_fp32_mul_final(const uint32_t* __restrict__ A,
                                     const uint32_t* __restrict__ B,
                                     uint32_t* __restrict__ out,
                                     int n_elems) {
    const int lane = threadIdx.x & 31;
    const int warp = (blockIdx.x * blockDim.x + threadIdx.x) >> 5;
    const int e0 = warp * ELEMS_PER_WARP;
    if (e0 >= n_elems) return;

    const int w = 31 - lane;  // memory word owned by this lane

    // Read burst: 16 outstanding LDG.32 per lane.
    uint32_t a[ELEMS_PER_WARP], b[ELEMS_PER_WARP];
#pragma unroll
    for (int i = 0; i < ELEMS_PER_WARP; ++i) {
        size_t off = (size_t)(e0 + i) * 32 + w;
        a[i] = __ldcs(A + off);
        b[i] = __ldcs(B + off);
    }

#pragma unroll
    for (int i = 0; i < ELEMS_PER_WARP; ++i) {
        // ballot bit l = (word 31-l != 0) = IEEE bit l. Direct pack.
        uint32_t ua = __ballot_sync(0xFFFFFFFFu, a[i] != 0u);
        uint32_t ub = __ballot_sync(0xFFFFFFFFu, b[i] != 0u);

        // IEEE-754 fp32 multiply, RNE, subnormal-aware (no -ftz).
        float p = __uint_as_float(ua) * __uint_as_float(ub);
        uint32_t up = __float_as_uint(p);

        // Lane l emits IEEE bit l as float 1.0f/0.0f bit pattern at word 31-l.
        uint32_t val = ((up >> lane) & 1u) ? 0x3F800000u : 0u;
        __stcs(out + (size_t)(e0 + i) * 32 + w, val);
    }
}

extern "C" void kernel_launch(void* const* d_in, const int* in_sizes, int n_in,
                              void* d_out, int out_size) {
    const uint32_t* A = (const uint32_t*)d_in[0];
    const uint32_t* B = (const uint32_t*)d_in[1];
    uint32_t* out = (uint32_t*)d_out;

    int n_elems = in_sizes[0] / 32;

    const int block = 256;  // 8 warps per block
    int warps_needed = (n_elems + ELEMS_PER_WARP - 1) / ELEMS_PER_WARP;
    int grid = (warps_needed * 32 + block - 1) / block;
    spike_fp32_mul_final<<<grid, block>>>(A, B, out, n_elems);
}